// round 16
// baseline (speedup 1.0000x reference)
#include <cuda_runtime.h>
#include <math.h>

#define W_IMG 512
#define H_IMG 512
#define MAX_N (32 * W_IMG * H_IMG)
#define MAX_WORDS (MAX_N / 64)
#define MAX_NODES (MAX_WORDS * 32)   // 32 slots per 64-px word
#define SENT 0x7F7F7F7F              // "I am root" sentinel (> any node id)

// Run-indexed node arrays.
__device__ int   g_lab[MAX_NODES];   // SENT = root; else parent/root id (< own id)
__device__ int   g_ar[MAX_NODES];    // area at roots; 0 at non-roots/unused
__device__ float g_rsum[MAX_NODES];  // per-run sum of (b-x); k_area folds to root
__device__ unsigned long long g_bits[MAX_WORDS];
// 0 = sum_fg bce/(w+1), 2 = sum_fg w, 3 = N_fg, 4 = sum_all b, 5 = sum_fg b
__device__ double g_acc[6];          // static zeros; k_final re-zeros each call

// ---------------------------------------------------------------------------
__device__ __forceinline__ int find_root(int x) {
    int p = g_lab[x];
    while (p < x) { x = p; p = g_lab[x]; }   // SENT > x  ->  x is root
    return x;
}

__device__ __forceinline__ void merge(int a, int b) {
    while (true) {
        a = find_root(a);
        b = find_root(b);
        if (a == b) return;
        if (a < b) { int t = a; a = b; b = t; }   // a = hi, b = lo
        int old = atomicMin(&g_lab[a], b);
        if (old >= a) return;   // a was root (old==SENT), now linked
        a = old;                // lost race; keep merging previous parent
    }
}

// node id of the run CONTAINING set bit k of word w with starts mask st
__device__ __forceinline__ int node_of(int w, unsigned long long st, int k) {
    return (w << 5) + __popcll(st & ((2ull << k) - 1ull)) - 1;
}

__device__ __forceinline__ int run_len(unsigned long long m, int k) {
    unsigned long long inv = ~(m >> k);
    return inv ? (__ffsll((long long)inv) - 1) : (64 - k);
}

__device__ __forceinline__ double warp_sum(double v) {
#pragma unroll
    for (int off = 16; off > 0; off >>= 1)
        v += __shfl_down_sync(0xFFFFFFFFu, v, off);
    return v;
}

// ---------------------------------------------------------------------------
// k_main: fused prep + streaming bce. Thread per 8 px (8 aligned lanes per
// 64-px word). Builds bits, inits node slots (coalesced int4), computes
// b sums and per-run rsum (one plain store per run via shfl head-exchange).
// ---------------------------------------------------------------------------
__global__ void k_main(const float* __restrict__ in,
                       const float* __restrict__ tgt, int nseg8) {
    float fAll = 0.f, fFg = 0.f;
    int t = blockIdx.x * blockDim.x + threadIdx.x;
    bool active = (t < nseg8);

    int w = t >> 3;
    int j = t & 7;
    int kk0 = j << 3;
    unsigned long long m = 0ull;
    unsigned int fgb = 0;
    float c[8];
    float head = 0.f, full = 0.f;

    if (active) {
        const float4* t4 = (const float4*)tgt;
        const float4* in4 = (const float4*)in;
        int q0 = t * 2;
        float4 a0 = __ldg(&t4[q0]);
        float4 a1 = __ldg(&t4[q0 + 1]);
        float4 v0 = __ldg(&in4[q0]);
        float4 v1 = __ldg(&in4[q0 + 1]);

        unsigned int b8 = 0;
        if (a0.x > 0.f) b8 |= 1u;
        if (a0.y > 0.f) b8 |= 2u;
        if (a0.z > 0.f) b8 |= 4u;
        if (a0.w > 0.f) b8 |= 8u;
        if (a1.x > 0.f) b8 |= 16u;
        if (a1.y > 0.f) b8 |= 32u;
        if (a1.z > 0.f) b8 |= 64u;
        if (a1.w > 0.f) b8 |= 128u;
        fgb = b8;

        unsigned long long mp = ((unsigned long long)b8) << kk0;
        mp |= __shfl_xor_sync(0xFFFFFFFFu, mp, 1);
        mp |= __shfl_xor_sync(0xFFFFFFFFu, mp, 2);
        mp |= __shfl_xor_sync(0xFFFFFFFFu, mp, 4);
        m = mp;
        if (j == 0) g_bits[w] = m;

        // coalesced node-slot init: 8 threads cover the word's 128B lines
        int wbase = w << 5;
        *(int4*)&g_lab[wbase + j * 4] = make_int4(SENT, SENT, SENT, SENT);
        *(int4*)&g_ar[wbase + j * 4] = make_int4(0, 0, 0, 0);

        float xs[8] = {v0.x, v0.y, v0.z, v0.w, v1.x, v1.y, v1.z, v1.w};
        float pf = 1.f;
#pragma unroll
        for (int l = 0; l < 8; l++) {
            float x = xs[l];
            float gpl = __logf(1.f + __expf(-fabsf(x)));
            float b = gpl + fmaxf(x, 0.f);     // bce if bg
            float sel = (float)((fgb >> l) & 1u);
            fAll += b;
            fFg += sel * b;
            c[l] = sel * (b - x);              // bce_fg contribution
            pf *= sel;
            head += pf * c[l];
        }
        full = (fgb == 0xFFu && j < 7) ? 1.f : 0.f;
    }

    float h1 = __shfl_down_sync(0xFFFFFFFFu, head, 1);
    float h2 = __shfl_down_sync(0xFFFFFFFFu, head, 2);
    float h3 = __shfl_down_sync(0xFFFFFFFFu, head, 3);
    float h4 = __shfl_down_sync(0xFFFFFFFFu, head, 4);
    float h5 = __shfl_down_sync(0xFFFFFFFFu, head, 5);
    float h6 = __shfl_down_sync(0xFFFFFFFFu, head, 6);
    float h7 = __shfl_down_sync(0xFFFFFFFFu, head, 7);
    float f1 = __shfl_down_sync(0xFFFFFFFFu, full, 1);
    float f2 = __shfl_down_sync(0xFFFFFFFFu, full, 2);
    float f3 = __shfl_down_sync(0xFFFFFFFFu, full, 3);
    float f4 = __shfl_down_sync(0xFFFFFFFFu, full, 4);
    float f5 = __shfl_down_sync(0xFFFFFFFFu, full, 5);
    float f6 = __shfl_down_sync(0xFFFFFFFFu, full, 6);
    float ext = h1 + f1 * (h2 + f2 * (h3 + f3 * (h4 + f4 * (h5 + f5 * (h6 + f6 * h7)))));

    if (active && fgb) {
        unsigned long long st = m & ~(m << 1);
        unsigned int prev_bit = (kk0 > 0) ? (unsigned int)((m >> (kk0 - 1)) & 1ull) : 0u;
        unsigned int next_bit = (j < 7) ? (unsigned int)((m >> (kk0 + 8)) & 1ull) : 0u;

        float cur = 0.f;
        bool owned = false;
#pragma unroll
        for (int l = 0; l < 8; l++) {
            bool fg = (fgb >> l) & 1u;
            if (fg) {
                bool pfg = (l == 0) ? (prev_bit != 0) : (((fgb >> (l - 1)) & 1u) != 0);
                if (!pfg) { owned = true; cur = 0.f; }
                cur += c[l];
                bool nfg = (l < 7) ? (((fgb >> (l + 1)) & 1u) != 0) : (next_bit != 0);
                if (owned && !nfg) {
                    g_rsum[node_of(w, st, kk0 + l)] = cur;        // run ends
                    owned = false;
                } else if (owned && l == 7) {
                    g_rsum[node_of(w, st, kk0 + 7)] = cur + ext;  // continues
                    owned = false;
                }
            }
        }
    }

    double d4 = fAll, d5 = fFg;
    __shared__ double sh[2][8];
    int lane = threadIdx.x & 31;
    int warp = threadIdx.x >> 5;
    d4 = warp_sum(d4); d5 = warp_sum(d5);
    if (lane == 0) { sh[0][warp] = d4; sh[1][warp] = d5; }
    __syncthreads();
    if (warp == 0) {
        int nw = blockDim.x >> 5;
        double v4 = (lane < nw) ? sh[0][lane] : 0.0;
        double v5 = (lane < nw) ? sh[1][lane] : 0.0;
        v4 = warp_sum(v4); v5 = warp_sum(v5);
        if (lane == 0) {
            atomicAdd(&g_acc[4], v4);
            atomicAdd(&g_acc[5], v5);
        }
    }
}

// ---------------------------------------------------------------------------
// k_union: word-level bitmask merges (run-indexed node ids)
// ---------------------------------------------------------------------------
__global__ void k_union(int nwords) {
    int w = blockIdx.x * blockDim.x + threadIdx.x;
    if (w >= nwords) return;
    unsigned long long cur = g_bits[w];
    if (!cur) return;
    unsigned long long stc = cur & ~(cur << 1);
    int wx = w & 7;
    int wy = (w >> 3) & (H_IMG - 1);

    if (wx && (cur & 1ull)) {
        unsigned long long L = g_bits[w - 1];
        if (L >> 63) {
            unsigned long long stl = L & ~(L << 1);
            merge((w << 5), ((w - 1) << 5) + __popcll(stl) - 1);
        }
    }
    if (wy) {
        unsigned long long up = g_bits[w - 8];
        unsigned long long ov = cur & up;
        if (ov) {
            unsigned long long stu = up & ~(up << 1);
            unsigned long long need = ov & ~(ov << 1);
            while (need) {
                int k = __ffsll((long long)need) - 1;
                need &= need - 1;
                merge(node_of(w, stc, k), node_of(w - 8, stu, k));
            }
        }
    }
}

// ---------------------------------------------------------------------------
// k_area: thread per quad; per owned run: compress, add length to root's
// area, and FOLD the run's rsum into the root's rsum (non-roots only).
// Safe: after union, roots are fixed points; rsum reads touch only
// non-root slots, writes only root slots.
// ---------------------------------------------------------------------------
__global__ void k_area(int nquad) {
    int t = blockIdx.x * blockDim.x + threadIdx.x;
    if (t >= nquad) return;
    int w = t >> 4;
    int b0 = (t & 15) << 2;
    unsigned long long m = __ldg(&g_bits[w]);
    unsigned long long st = m & ~(m << 1);
    unsigned int s = (unsigned int)((st >> b0) & 0xFull);
    if (!s) return;
    int wbase = w << 5;
    while (s) {
        int k = __ffs(s) - 1;
        s &= s - 1;
        int kk = b0 + k;
        int node = wbase + __popcll(st & ((1ull << kk) - 1ull));
        int root = find_root(node);
        atomicAdd(&g_ar[root], run_len(m, kk));
        if (root != node) {
            g_lab[node] = root;                       // compress
            atomicAdd(&g_rsum[root], g_rsum[node]);   // fold rsum to root
        }
    }
}

// ---------------------------------------------------------------------------
// k_post: PURE COALESCED SWEEP, zero gathers. Thread per 4 slots:
// int4 ar + float4 rsum. ar>0 <=> used root (atomicAdds target roots only).
// f0 += rsum_total/(sqrt(a)+1); f2 += a^1.5; f3 += a.
// ---------------------------------------------------------------------------
__global__ void k_post(int nvec) {
    double d0 = 0.0, d2 = 0.0, d3 = 0.0;
    int t = blockIdx.x * blockDim.x + threadIdx.x;
    if (t < nvec) {
        int4 av = __ldg(&((const int4*)g_ar)[t]);
        float4 rv = __ldg(&((const float4*)g_rsum)[t]);
        int as[4] = {av.x, av.y, av.z, av.w};
        float rs[4] = {rv.x, rv.y, rv.z, rv.w};

        float f0 = 0.f, f2 = 0.f, f3 = 0.f;
#pragma unroll
        for (int l = 0; l < 4; l++) {
            float a = (float)as[l];
            float sq = sqrtf(a);
            bool used = as[l] > 0;
            f0 += used ? rs[l] * __fdividef(1.f, sq + 1.f) : 0.f;
            f2 += used ? a * sq : 0.f;
            f3 += used ? a : 0.f;
        }
        d0 = f0; d2 = f2; d3 = f3;
    }

    __shared__ double sh[3][8];
    int lane = threadIdx.x & 31;
    int warp = threadIdx.x >> 5;
    d0 = warp_sum(d0); d2 = warp_sum(d2); d3 = warp_sum(d3);
    if (lane == 0) { sh[0][warp] = d0; sh[1][warp] = d2; sh[2][warp] = d3; }
    __syncthreads();
    if (warp == 0) {
        int nw = blockDim.x >> 5;
        double v0 = (lane < nw) ? sh[0][lane] : 0.0;
        double v2 = (lane < nw) ? sh[1][lane] : 0.0;
        double v3 = (lane < nw) ? sh[2][lane] : 0.0;
        v0 = warp_sum(v0); v2 = warp_sum(v2); v3 = warp_sum(v3);
        if (lane == 0) {
            atomicAdd(&g_acc[0], v0);
            atomicAdd(&g_acc[2], v2);
            atomicAdd(&g_acc[3], v3);
        }
    }
}

// ---------------------------------------------------------------------------
// k_final: combine, write output, and RE-ZERO g_acc so the next graph
// replay starts clean (module-load static zeros cover the first call).
// ---------------------------------------------------------------------------
__global__ void k_final(float* __restrict__ out, double inv_n) {
    double nfg = g_acc[3];
    double mean_nz = g_acc[2] / (nfg > 0.0 ? nfg : 1.0);
    double f1 = g_acc[4] - g_acc[5];   // Σ_bg b = Σ_all b - Σ_fg b
    double loss = (g_acc[0] + f1 / (mean_nz + 1.0)) * inv_n;
    out[0] = (float)loss;
#pragma unroll
    for (int i = 0; i < 6; i++) g_acc[i] = 0.0;
}

// ---------------------------------------------------------------------------
extern "C" void kernel_launch(void* const* d_in, const int* in_sizes, int n_in,
                              void* d_out, int out_size) {
    const float* inputs  = (const float*)d_in[0];
    const float* targets = (const float*)d_in[1];
    float* out = (float*)d_out;

    int n = in_sizes[0];
    int nwords = n >> 6;
    int nquad = n >> 2;
    int nseg8 = n >> 3;
    int nvec = nwords * 8;          // (nwords*32) / 4 slots per thread
    const int threads = 256;
    int sblocks = (nseg8 + threads - 1) / threads;
    int wblocks = (nwords + threads - 1) / threads;
    int qblocks = (nquad + threads - 1) / threads;
    int pblocks = (nvec + threads - 1) / threads;

    k_main<<<sblocks, threads>>>(inputs, targets, nseg8);
    k_union<<<wblocks, threads>>>(nwords);
    k_area<<<qblocks, threads>>>(nquad);
    k_post<<<pblocks, threads>>>(nvec);
    k_final<<<1, 1>>>(out, 1.0 / (double)n);
}

// round 17
// speedup vs baseline: 1.0371x; 1.0371x over previous
#include <cuda_runtime.h>
#include <math.h>

#define W_IMG 512
#define H_IMG 512
#define MAX_N (32 * W_IMG * H_IMG)
#define MAX_WORDS (MAX_N / 64)
#define MAX_NODES (MAX_WORDS * 32)   // 32 slots per 64-px word
#define SENT 0x7F7F7F7F              // "I am root" sentinel (> any node id)

// Run-indexed node arrays.
__device__ int   g_lab[MAX_NODES];   // SENT = root; else parent/root id (< own id)
__device__ int   g_ar[MAX_NODES];    // area at roots; 0 elsewhere
__device__ float g_rsum[MAX_NODES];  // per-run sum of (b-x); folded to root in area
__device__ unsigned long long g_bits[MAX_WORDS];
// 0 = sum_fg bce/(w+1), 2 = sum_fg w, 3 = N_fg, 4 = sum_all b, 5 = sum_fg b
__device__ double g_acc[6];          // static zeros; final phase re-zeros

// Software grid barrier state (static zeros; sense grows monotonically).
__device__ unsigned g_count;
__device__ volatile unsigned g_sense;

// ---------------------------------------------------------------------------
__device__ __forceinline__ void gbar(unsigned* sgen) {
    __syncthreads();
    if (threadIdx.x == 0) {
        unsigned gen = *sgen;
        __threadfence();
        if (atomicAdd(&g_count, 1u) == gridDim.x - 1) {
            g_count = 0;
            __threadfence();
            g_sense = gen + 1;                   // release
        } else {
            while (g_sense == gen) __nanosleep(64);
            __threadfence();                     // acquire
        }
        *sgen = gen + 1;
    }
    __syncthreads();
}

// ---------------------------------------------------------------------------
__device__ __forceinline__ int find_root(int x) {
    int p = __ldcg(&g_lab[x]);
    while (p < x) { x = p; p = __ldcg(&g_lab[x]); }   // SENT > x -> root
    return x;
}

__device__ __forceinline__ void merge(int a, int b) {
    while (true) {
        a = find_root(a);
        b = find_root(b);
        if (a == b) return;
        if (a < b) { int t = a; a = b; b = t; }   // a = hi, b = lo
        int old = atomicMin(&g_lab[a], b);
        if (old >= a) return;   // a was root (old==SENT), now linked
        a = old;
    }
}

__device__ __forceinline__ int node_of(int w, unsigned long long st, int k) {
    return (w << 5) + __popcll(st & ((2ull << k) - 1ull)) - 1;
}

__device__ __forceinline__ int run_len(unsigned long long m, int k) {
    unsigned long long inv = ~(m >> k);
    return inv ? (__ffsll((long long)inv) - 1) : (64 - k);
}

__device__ __forceinline__ double warp_sum(double v) {
#pragma unroll
    for (int off = 16; off > 0; off >>= 1)
        v += __shfl_down_sync(0xFFFFFFFFu, v, off);
    return v;
}

// block-reduce helper: reduces up to 3 doubles, adds to g_acc slots
__device__ __forceinline__ void block_acc3(double a, double b, double c,
                                           int ia, int ib, int ic,
                                           double sh[3][8]) {
    int lane = threadIdx.x & 31;
    int warp = threadIdx.x >> 5;
    a = warp_sum(a); b = warp_sum(b); c = warp_sum(c);
    if (lane == 0) { sh[0][warp] = a; sh[1][warp] = b; sh[2][warp] = c; }
    __syncthreads();
    if (warp == 0) {
        int nw = blockDim.x >> 5;
        double v0 = (lane < nw) ? sh[0][lane] : 0.0;
        double v1 = (lane < nw) ? sh[1][lane] : 0.0;
        double v2 = (lane < nw) ? sh[2][lane] : 0.0;
        v0 = warp_sum(v0); v1 = warp_sum(v1); v2 = warp_sum(v2);
        if (lane == 0) {
            if (ia >= 0) atomicAdd(&g_acc[ia], v0);
            if (ib >= 0) atomicAdd(&g_acc[ib], v1);
            if (ic >= 0) atomicAdd(&g_acc[ic], v2);
        }
    }
    __syncthreads();
}

// ---------------------------------------------------------------------------
// k_all: ALL phases in one persistent kernel with software grid barriers.
// ---------------------------------------------------------------------------
__global__ void __launch_bounds__(256) k_all(const float* __restrict__ in,
                                             const float* __restrict__ tgt,
                                             float* __restrict__ out, int n) {
    int tid = threadIdx.x;
    int gid = blockIdx.x * blockDim.x + tid;
    int T = gridDim.x * blockDim.x;
    int nwords = n >> 6, nseg8 = n >> 3, nquad = n >> 2, nvec = nwords * 8;

    __shared__ unsigned sgen;
    __shared__ double sh[3][8];
    if (tid == 0) sgen = g_sense;
    __syncthreads();

    // ======== PHASE 1: main (prep + streaming bce) — thread per 8 px ========
    float fAll = 0.f, fFg = 0.f;
    for (int base = 0; base < nseg8; base += T) {
        int t = base + gid;
        bool active = t < nseg8;       // warp-uniform (boundaries multiple of 256)
        int w = t >> 3, j = t & 7, kk0 = j << 3;
        unsigned long long m = 0ull;
        unsigned int fgb = 0;
        float c[8];
        float head = 0.f, full = 0.f;

        if (active) {
            const float4* t4 = (const float4*)tgt;
            const float4* in4 = (const float4*)in;
            int q0 = t * 2;
            float4 a0 = __ldg(&t4[q0]);
            float4 a1 = __ldg(&t4[q0 + 1]);
            float4 v0 = __ldg(&in4[q0]);
            float4 v1 = __ldg(&in4[q0 + 1]);

            unsigned int b8 = 0;
            if (a0.x > 0.f) b8 |= 1u;
            if (a0.y > 0.f) b8 |= 2u;
            if (a0.z > 0.f) b8 |= 4u;
            if (a0.w > 0.f) b8 |= 8u;
            if (a1.x > 0.f) b8 |= 16u;
            if (a1.y > 0.f) b8 |= 32u;
            if (a1.z > 0.f) b8 |= 64u;
            if (a1.w > 0.f) b8 |= 128u;
            fgb = b8;

            unsigned long long mp = ((unsigned long long)b8) << kk0;
            mp |= __shfl_xor_sync(0xFFFFFFFFu, mp, 1);
            mp |= __shfl_xor_sync(0xFFFFFFFFu, mp, 2);
            mp |= __shfl_xor_sync(0xFFFFFFFFu, mp, 4);
            m = mp;
            if (j == 0) g_bits[w] = m;

            // coalesced node-slot init
            int wbase = w << 5;
            *(int4*)&g_lab[wbase + j * 4] = make_int4(SENT, SENT, SENT, SENT);
            *(int4*)&g_ar[wbase + j * 4] = make_int4(0, 0, 0, 0);

            float xs[8] = {v0.x, v0.y, v0.z, v0.w, v1.x, v1.y, v1.z, v1.w};
            float pf = 1.f;
#pragma unroll
            for (int l = 0; l < 8; l++) {
                float x = xs[l];
                float gpl = __logf(1.f + __expf(-fabsf(x)));
                float b = gpl + fmaxf(x, 0.f);      // bce if bg
                float sel = (float)((fgb >> l) & 1u);
                fAll += b;
                fFg += sel * b;
                c[l] = sel * (b - x);               // bce_fg contribution
                pf *= sel;
                head += pf * c[l];
            }
            full = (fgb == 0xFFu && j < 7) ? 1.f : 0.f;
        }

        float h1 = __shfl_down_sync(0xFFFFFFFFu, head, 1);
        float h2 = __shfl_down_sync(0xFFFFFFFFu, head, 2);
        float h3 = __shfl_down_sync(0xFFFFFFFFu, head, 3);
        float h4 = __shfl_down_sync(0xFFFFFFFFu, head, 4);
        float h5 = __shfl_down_sync(0xFFFFFFFFu, head, 5);
        float h6 = __shfl_down_sync(0xFFFFFFFFu, head, 6);
        float h7 = __shfl_down_sync(0xFFFFFFFFu, head, 7);
        float f1 = __shfl_down_sync(0xFFFFFFFFu, full, 1);
        float f2 = __shfl_down_sync(0xFFFFFFFFu, full, 2);
        float f3 = __shfl_down_sync(0xFFFFFFFFu, full, 3);
        float f4 = __shfl_down_sync(0xFFFFFFFFu, full, 4);
        float f5 = __shfl_down_sync(0xFFFFFFFFu, full, 5);
        float f6 = __shfl_down_sync(0xFFFFFFFFu, full, 6);
        float ext = h1 + f1 * (h2 + f2 * (h3 + f3 * (h4 + f4 * (h5 + f5 * (h6 + f6 * h7)))));

        if (active && fgb) {
            unsigned long long st = m & ~(m << 1);
            unsigned int prev_bit = (kk0 > 0) ? (unsigned int)((m >> (kk0 - 1)) & 1ull) : 0u;
            unsigned int next_bit = (j < 7) ? (unsigned int)((m >> (kk0 + 8)) & 1ull) : 0u;

            float cur = 0.f;
            bool owned = false;
#pragma unroll
            for (int l = 0; l < 8; l++) {
                bool fg = (fgb >> l) & 1u;
                if (fg) {
                    bool pfg = (l == 0) ? (prev_bit != 0) : (((fgb >> (l - 1)) & 1u) != 0);
                    if (!pfg) { owned = true; cur = 0.f; }
                    cur += c[l];
                    bool nfg = (l < 7) ? (((fgb >> (l + 1)) & 1u) != 0) : (next_bit != 0);
                    if (owned && !nfg) {
                        g_rsum[node_of(w, st, kk0 + l)] = cur;        // run ends
                        owned = false;
                    } else if (owned && l == 7) {
                        g_rsum[node_of(w, st, kk0 + 7)] = cur + ext;  // continues
                        owned = false;
                    }
                }
            }
        }
    }
    block_acc3((double)fAll, (double)fFg, 0.0, 4, 5, -1, sh);
    gbar(&sgen);

    // ======== PHASE 2: union — word-level merges ========
    for (int base = 0; base < nwords; base += T) {
        int w = base + gid;
        if (w < nwords) {
            unsigned long long cur = __ldcg(&g_bits[w]);
            if (cur) {
                unsigned long long stc = cur & ~(cur << 1);
                int wx = w & 7;
                int wy = (w >> 3) & (H_IMG - 1);
                if (wx && (cur & 1ull)) {
                    unsigned long long L = __ldcg(&g_bits[w - 1]);
                    if (L >> 63) {
                        unsigned long long stl = L & ~(L << 1);
                        merge((w << 5), ((w - 1) << 5) + __popcll(stl) - 1);
                    }
                }
                if (wy) {
                    unsigned long long up = __ldcg(&g_bits[w - 8]);
                    unsigned long long ov = cur & up;
                    if (ov) {
                        unsigned long long stu = up & ~(up << 1);
                        unsigned long long need = ov & ~(ov << 1);
                        while (need) {
                            int k = __ffsll((long long)need) - 1;
                            need &= need - 1;
                            merge(node_of(w, stc, k), node_of(w - 8, stu, k));
                        }
                    }
                }
            }
        }
    }
    gbar(&sgen);

    // ======== PHASE 3: area — compress, accumulate area, fold rsum ========
    for (int base = 0; base < nquad; base += T) {
        int t = base + gid;
        if (t < nquad) {
            int w = t >> 4;
            int b0 = (t & 15) << 2;
            unsigned long long m = __ldcg(&g_bits[w]);
            unsigned long long st = m & ~(m << 1);
            unsigned int s = (unsigned int)((st >> b0) & 0xFull);
            if (s) {
                int wbase = w << 5;
                while (s) {
                    int k = __ffs(s) - 1;
                    s &= s - 1;
                    int kk = b0 + k;
                    int node = wbase + __popcll(st & ((1ull << kk) - 1ull));
                    int root = find_root(node);
                    atomicAdd(&g_ar[root], run_len(m, kk));
                    if (root != node)
                        atomicAdd(&g_rsum[root], __ldcg(&g_rsum[node]));
                }
            }
        }
    }
    gbar(&sgen);

    // ======== PHASE 4: post — pure coalesced sweep (ar>0 <=> used root) ====
    {
        float f0 = 0.f, f2 = 0.f, f3 = 0.f;
        for (int base = 0; base < nvec; base += T) {
            int t = base + gid;
            if (t < nvec) {
                int4 av = __ldcg(&((const int4*)g_ar)[t]);
                float4 rv = __ldcg(&((const float4*)g_rsum)[t]);
                int as[4] = {av.x, av.y, av.z, av.w};
                float rs[4] = {rv.x, rv.y, rv.z, rv.w};
#pragma unroll
                for (int l = 0; l < 4; l++) {
                    float a = (float)as[l];
                    float sq = sqrtf(a);
                    bool used = as[l] > 0;
                    f0 += used ? rs[l] * __fdividef(1.f, sq + 1.f) : 0.f;
                    f2 += used ? a * sq : 0.f;
                    f3 += used ? a : 0.f;
                }
            }
        }
        block_acc3((double)f0, (double)f2, (double)f3, 0, 2, 3, sh);
    }
    gbar(&sgen);

    // ======== PHASE 5: final ========
    if (gid == 0) {
        double nfg = __ldcg((const double*)&g_acc[3]);
        double s2  = __ldcg((const double*)&g_acc[2]);
        double s0  = __ldcg((const double*)&g_acc[0]);
        double s4  = __ldcg((const double*)&g_acc[4]);
        double s5  = __ldcg((const double*)&g_acc[5]);
        double mean_nz = s2 / (nfg > 0.0 ? nfg : 1.0);
        double f1 = s4 - s5;                     // Σ_bg b
        double loss = (s0 + f1 / (mean_nz + 1.0)) / (double)n;
        out[0] = (float)loss;
#pragma unroll
        for (int i = 0; i < 6; i++) g_acc[i] = 0.0;   // clean for next replay
    }
}

// ---------------------------------------------------------------------------
extern "C" void kernel_launch(void* const* d_in, const int* in_sizes, int n_in,
                              void* d_out, int out_size) {
    const float* inputs  = (const float*)d_in[0];
    const float* targets = (const float*)d_in[1];
    float* out = (float*)d_out;
    int n = in_sizes[0];

    // exact co-residency: software grid barrier requires all blocks resident
    int dev = 0, sms = 0, nb = 0;
    cudaGetDevice(&dev);
    cudaDeviceGetAttribute(&sms, cudaDevAttrMultiProcessorCount, dev);
    cudaOccupancyMaxActiveBlocksPerMultiprocessor(&nb, k_all, 256, 0);
    if (nb < 1) nb = 1;
    int grid = sms * nb;

    k_all<<<grid, 256>>>(inputs, targets, out, n);
}